// round 3
// baseline (speedup 1.0000x reference)
#include <cuda_runtime.h>
#include <math.h>
#include <stdint.h>

#define D_MODEL 1024
#define D_FF    4096
#define NE      8
#define T_TOK   4096
#define MAXROWS 9216      // 8192 rows + 8 experts * 128-pad
#define MAXTILES 72

// ---------------- scratch (static device memory: allocation-free) -------------
__device__ float g_act[(size_t)MAXROWS * D_FF];     // expert-grouped FFN1 activations
__device__ float g_y[(size_t)MAXROWS * D_MODEL];    // expert-grouped FFN2 outputs
__device__ int   g_rowtok[MAXROWS];
__device__ int   g_cnt[NE];
__device__ int   g_cnt2[NE];
__device__ int   g_off[NE];
__device__ int   g_tileE[MAXTILES];
__device__ int   g_tokE[T_TOK * 2];
__device__ float g_tokW[T_TOK * 2];
__device__ int   g_loc[T_TOK * 2];

// ---------------- helpers ----------------------------------------------------
__device__ __forceinline__ unsigned f2tf(float f) {
    unsigned u;
    asm("cvt.rna.tf32.f32 %0, %1;" : "=r"(u) : "f"(f));
    return u;
}

__device__ __forceinline__ void mma8(float (&d)[4], const unsigned (&a)[4],
                                     unsigned b0, unsigned b1) {
    asm volatile(
        "mma.sync.aligned.m16n8k8.row.col.f32.tf32.tf32.f32 "
        "{%0,%1,%2,%3}, {%4,%5,%6,%7}, {%8,%9}, {%0,%1,%2,%3};\n"
        : "+f"(d[0]), "+f"(d[1]), "+f"(d[2]), "+f"(d[3])
        : "r"(a[0]), "r"(a[1]), "r"(a[2]), "r"(a[3]), "r"(b0), "r"(b1));
}

__device__ __forceinline__ float act_gelu(float h) {
    return 0.5f * h * (1.0f + erff(h * 0.70710678118654752f));
}
__device__ __forceinline__ float act_silu(float h) {
    return h / (1.0f + __expf(-h));
}

// ---------------- stage 0: init ----------------------------------------------
__global__ void init_kernel() {
    int i = blockIdx.x * blockDim.x + threadIdx.x;
    if (i < NE) { g_cnt[i] = 0; g_cnt2[i] = 0; }
    if (i < MAXROWS) g_rowtok[i] = -1;
}

// ---------------- stage 1: gate (fp32 exact) ---------------------------------
__global__ void gate_kernel(const float* __restrict__ x,
                            const float* __restrict__ Wg,
                            const float* __restrict__ bg) {
    int wid = threadIdx.x >> 5, lane = threadIdx.x & 31;
    int t = blockIdx.x * 8 + wid;
    const float* xr = x + (size_t)t * D_MODEL;
    float acc[8] = {0, 0, 0, 0, 0, 0, 0, 0};
    for (int d = lane; d < D_MODEL; d += 32) {
        float xv = xr[d];
        const float4* w = (const float4*)(Wg + d * 8);
        float4 w0 = w[0], w1 = w[1];
        acc[0] += xv * w0.x; acc[1] += xv * w0.y;
        acc[2] += xv * w0.z; acc[3] += xv * w0.w;
        acc[4] += xv * w1.x; acc[5] += xv * w1.y;
        acc[6] += xv * w1.z; acc[7] += xv * w1.w;
    }
#pragma unroll
    for (int o = 16; o > 0; o >>= 1)
#pragma unroll
        for (int e = 0; e < 8; e++)
            acc[e] += __shfl_xor_sync(0xffffffffu, acc[e], o);
    if (lane == 0) {
        float v0 = -1e30f, v1 = -1e30f;
        int i0 = 0, i1 = 0;
#pragma unroll
        for (int e = 0; e < 8; e++) {
            float v = acc[e] + bg[e];
            if (v > v0) { v1 = v0; i1 = i0; v0 = v; i0 = e; }
            else if (v > v1) { v1 = v; i1 = e; }
        }
        float e1 = expf(v1 - v0);
        float inv = 1.0f / (1.0f + e1);
        g_tokE[t * 2]     = i0; g_tokW[t * 2]     = inv;
        g_tokE[t * 2 + 1] = i1; g_tokW[t * 2 + 1] = e1 * inv;
        atomicAdd(&g_cnt[i0], 1);
        atomicAdd(&g_cnt[i1], 1);
    }
}

// ---------------- stage 2: plan (offsets + tile->expert map) ------------------
__global__ void plan_kernel() {
    if (threadIdx.x == 0 && blockIdx.x == 0) {
        int ofs = 0;
        for (int e = 0; e < NE; e++) {
            g_off[e] = ofs;
            int nt = (g_cnt[e] + 127) >> 7;
            int t0 = ofs >> 7;
            for (int j = 0; j < nt; j++) g_tileE[t0 + j] = e;
            ofs += nt << 7;
        }
        for (int t = ofs >> 7; t < MAXTILES; t++) g_tileE[t] = -1;
    }
}

// ---------------- stage 3: scatter tokens into expert rows --------------------
__global__ void scatter_kernel() {
    int i = blockIdx.x * blockDim.x + threadIdx.x;
    if (i >= T_TOK * 2) return;
    int e = g_tokE[i];
    int s = atomicAdd(&g_cnt2[e], 1);
    int row = g_off[e] + s;
    g_rowtok[row] = i >> 1;
    g_loc[i] = row;
}

// ---------------- stage 4/5: tiled TF32 GEMM ----------------------------------
// CTA tile 128(M) x 128(N) x 32(K), 256 threads, 8 warps (4x2), warp 32x64.
// Smem layouts: As[m][k] stride 36 (conflict-free frag LDS & STS.128),
//               Bs[k][n] stride 136 (conflict-free frag LDS & STS.128).
template <int KTOT, int NTOT, bool FFN1>
__global__ __launch_bounds__(256) void ffn_kernel(const float* __restrict__ X,
                                                  const float* __restrict__ W,
                                                  const float* __restrict__ bias) {
    extern __shared__ unsigned sm[];
    constexpr int NT = NTOT / 128;
    constexpr int NC = KTOT / 32;
    constexpr int ASZ = 128 * 36;
    constexpr int BSZ = 32 * 136;

    // L2-friendly swizzle: groups of 8 m-tiles x all n-tiles
    int bid = blockIdx.x;
    int gid = bid / (8 * NT), rem = bid % (8 * NT);
    int mt = gid * 8 + (rem & 7);
    int nt = rem >> 3;
    int e = g_tileE[mt];
    if (e < 0) return;

    const float* Wb = W + (size_t)e * ((size_t)D_MODEL * D_FF);
    const float* bb = bias + e * NTOT;
    const float* A = FFN1 ? X : (const float*)g_act;
    float* Out = FFN1 ? (float*)g_act : (float*)g_y;
    int n0 = nt * 128;

    int tid = threadIdx.x, lane = tid & 31, wid = tid >> 5;
    int wm = wid >> 1, wn = wid & 1, lr = lane >> 2, lc = lane & 3;

    // A global-load mapping: f4id = tid + t*256; row = f4id>>3 ; kq = f4id&7
    int r0 = tid >> 3, kq = tid & 7;
    const float* aP[4];
#pragma unroll
    for (int t = 0; t < 4; t++) {
        int row = mt * 128 + r0 + t * 32;
        if (FFN1) {
            int tok = g_rowtok[row];
            aP[t] = (tok >= 0) ? (A + (size_t)tok * KTOT + kq * 4) : nullptr;
        } else {
            aP[t] = A + (size_t)row * KTOT + kq * 4;
        }
    }
    // B global-load mapping: krow = (tid>>5)+t*8 ; nq = tid&31
    int nq = tid & 31, kr0 = tid >> 5;
    const float* bP[4];
#pragma unroll
    for (int t = 0; t < 4; t++)
        bP[t] = Wb + (size_t)(kr0 + t * 8) * NTOT + n0 + nq * 4;

    unsigned* As = sm;               // 2 * ASZ
    unsigned* Bs = sm + 2 * ASZ;     // 2 * BSZ

    float acc[2][8][4];
#pragma unroll
    for (int i = 0; i < 2; i++)
#pragma unroll
        for (int j = 0; j < 8; j++)
#pragma unroll
            for (int k = 0; k < 4; k++) acc[i][j][k] = 0.0f;

    float4 ra[4], rb[4];

    auto ldA = [&](int k0) {
#pragma unroll
        for (int t = 0; t < 4; t++)
            ra[t] = aP[t] ? *(const float4*)(aP[t] + k0)
                          : make_float4(0.f, 0.f, 0.f, 0.f);
    };
    auto ldB = [&](int k0) {
#pragma unroll
        for (int t = 0; t < 4; t++)
            rb[t] = *(const float4*)(bP[t] + (size_t)k0 * NTOT);
    };
    auto sts = [&](int buf) {
        unsigned* a = As + buf * ASZ;
        unsigned* b = Bs + buf * BSZ;
#pragma unroll
        for (int t = 0; t < 4; t++) {
            unsigned* p = a + (r0 + t * 32) * 36 + kq * 4;
            *(uint4*)p = make_uint4(f2tf(ra[t].x), f2tf(ra[t].y),
                                    f2tf(ra[t].z), f2tf(ra[t].w));
        }
#pragma unroll
        for (int t = 0; t < 4; t++) {
            unsigned* p = b + (kr0 + t * 8) * 136 + nq * 4;
            *(uint4*)p = make_uint4(f2tf(rb[t].x), f2tf(rb[t].y),
                                    f2tf(rb[t].z), f2tf(rb[t].w));
        }
    };
    auto compute = [&](int buf) {
        const unsigned* a_ = As + buf * ASZ;
        const unsigned* b_ = Bs + buf * BSZ;
#pragma unroll
        for (int ks = 0; ks < 4; ks++) {
            int kk = ks * 8;
            unsigned afr[2][4];
#pragma unroll
            for (int mf = 0; mf < 2; mf++) {
                int mrow = wm * 32 + mf * 16 + lr;
                afr[mf][0] = a_[(mrow)     * 36 + kk + lc];
                afr[mf][1] = a_[(mrow + 8) * 36 + kk + lc];
                afr[mf][2] = a_[(mrow)     * 36 + kk + lc + 4];
                afr[mf][3] = a_[(mrow + 8) * 36 + kk + lc + 4];
            }
#pragma unroll
            for (int nf = 0; nf < 8; nf++) {
                int ncol = wn * 64 + nf * 8 + lr;
                unsigned b0 = b_[(kk + lc)     * 136 + ncol];
                unsigned b1 = b_[(kk + lc + 4) * 136 + ncol];
                mma8(acc[0][nf], afr[0], b0, b1);
                mma8(acc[1][nf], afr[1], b0, b1);
            }
        }
    };

    ldA(0); ldB(0); sts(0);
    __syncthreads();
#pragma unroll 2
    for (int c = 0; c < NC; c++) {
        int k0n = (c + 1) * 32;
        if (c + 1 < NC) { ldA(k0n); ldB(k0n); }
        compute(c & 1);
        if (c + 1 < NC) sts((c + 1) & 1);
        __syncthreads();
    }

    // epilogue
    bool isGelu = !(e & 1);
#pragma unroll
    for (int mf = 0; mf < 2; mf++) {
#pragma unroll
        for (int nf = 0; nf < 8; nf++) {
            int row = mt * 128 + wm * 32 + mf * 16 + lr;
            int col = n0 + wn * 64 + nf * 8 + 2 * lc;
            float b0v = bb[col], b1v = bb[col + 1];
            float v00 = acc[mf][nf][0] + b0v;
            float v01 = acc[mf][nf][1] + b1v;
            float v10 = acc[mf][nf][2] + b0v;
            float v11 = acc[mf][nf][3] + b1v;
            if (FFN1) {
                if (isGelu) {
                    v00 = act_gelu(v00); v01 = act_gelu(v01);
                    v10 = act_gelu(v10); v11 = act_gelu(v11);
                } else {
                    v00 = act_silu(v00); v01 = act_silu(v01);
                    v10 = act_silu(v10); v11 = act_silu(v11);
                }
            }
            *(float2*)(Out + (size_t)row * NTOT + col) = make_float2(v00, v01);
            *(float2*)(Out + (size_t)(row + 8) * NTOT + col) = make_float2(v10, v11);
        }
    }
}

// ---------------- stage 6: combine (deterministic gather, no atomics) ---------
__global__ void combine_kernel(float* __restrict__ out) {
    int t = blockIdx.x, c = threadIdx.x;
    float w0 = g_tokW[t * 2], w1 = g_tokW[t * 2 + 1];
    int l0 = g_loc[t * 2], l1 = g_loc[t * 2 + 1];
    const float4 y0 = *(const float4*)(g_y + (size_t)l0 * D_MODEL + c * 4);
    const float4 y1 = *(const float4*)(g_y + (size_t)l1 * D_MODEL + c * 4);
    float4 o;
    o.x = w0 * y0.x + w1 * y1.x;
    o.y = w0 * y0.y + w1 * y1.y;
    o.z = w0 * y0.z + w1 * y1.z;
    o.w = w0 * y0.w + w1 * y1.w;
    *(float4*)(out + (size_t)t * D_MODEL + c * 4) = o;
}

// ---------------- host launcher ----------------------------------------------
extern "C" void kernel_launch(void* const* d_in, const int* in_sizes, int n_in,
                              void* d_out, int out_size) {
    const float* x  = (const float*)d_in[0];
    const float* W1 = (const float*)d_in[1];
    const float* b1 = (const float*)d_in[2];
    const float* W2 = (const float*)d_in[3];
    const float* b2 = (const float*)d_in[4];
    const float* Wg = (const float*)d_in[5];
    const float* bg = (const float*)d_in[6];
    float* out = (float*)d_out;

    const int SMEM = (2 * 128 * 36 + 2 * 32 * 136) * 4;  // 71680 bytes
    cudaFuncSetAttribute(ffn_kernel<D_MODEL, D_FF, true>,
                         cudaFuncAttributeMaxDynamicSharedMemorySize, SMEM);
    cudaFuncSetAttribute(ffn_kernel<D_FF, D_MODEL, false>,
                         cudaFuncAttributeMaxDynamicSharedMemorySize, SMEM);

    init_kernel<<<(MAXROWS + 255) / 256, 256>>>();
    gate_kernel<<<T_TOK / 8, 256>>>(x, Wg, bg);
    plan_kernel<<<1, 1>>>();
    scatter_kernel<<<(T_TOK * 2) / 256, 256>>>();
    // FFN1: 72 m-tiles x 32 n-tiles
    ffn_kernel<D_MODEL, D_FF, true><<<MAXTILES * (D_FF / 128), 256, SMEM>>>(x, W1, b1);
    // FFN2: 72 m-tiles x 8 n-tiles
    ffn_kernel<D_FF, D_MODEL, false><<<MAXTILES * (D_MODEL / 128), 256, SMEM>>>(nullptr, W2, b2);
    combine_kernel<<<T_TOK, 256>>>(out);
}

// round 6
// speedup vs baseline: 1.8541x; 1.8541x over previous
#include <cuda_runtime.h>
#include <math.h>
#include <stdint.h>

#define D_MODEL 1024
#define D_FF    4096
#define NE      8
#define T_TOK   4096
#define MAXROWS 9216      // 8192 rows + 8 experts * 128-pad
#define MAXTILES 72

// GEMM tiling
#define NSTAGE 3
#define ASZ    4608          // A stage words: 128 rows * 36 (stride, conflict-free)
#define BSZ    8448          // B stage words: 32 rows * 264 (stride, conflict-free)
#define STAGEW (ASZ + BSZ)   // 13056 words
#define STAGE_BYTES (STAGEW * 4)   // 52224 B
#define SMEM_TOTAL (NSTAGE * STAGE_BYTES)  // 156672 B

// ---------------- scratch (static device memory: allocation-free) -------------
__device__ float g_act[(size_t)MAXROWS * D_FF];     // FFN1 activations (tf32-rounded)
__device__ float g_y[(size_t)MAXROWS * D_MODEL];    // FFN2 outputs (fp32)
__device__ float g_xg[(size_t)MAXROWS * D_MODEL];   // gathered tokens (tf32-rounded)
__device__ float g_w1r[(size_t)NE * D_MODEL * D_FF];  // W1 tf32-rounded copy [E][D][F]
__device__ float g_w2r[(size_t)NE * D_FF * D_MODEL];  // W2 tf32-rounded copy [E][F][D]
__device__ int   g_rowtok[MAXROWS];
__device__ int   g_cnt[NE];
__device__ int   g_cnt2[NE];
__device__ int   g_off[NE];
__device__ int   g_tileE[MAXTILES];
__device__ int   g_tokE[T_TOK * 2];
__device__ float g_tokW[T_TOK * 2];
__device__ int   g_loc[T_TOK * 2];

// ---------------- helpers ----------------------------------------------------
__device__ __forceinline__ unsigned f2tf(float f) {
    unsigned u;
    asm("cvt.rna.tf32.f32 %0, %1;" : "=r"(u) : "f"(f));
    return u;
}
__device__ __forceinline__ uint32_t smem_u32(const void* p) {
    uint32_t a;
    asm("{ .reg .u64 t; cvta.to.shared.u64 t, %1; cvt.u32.u64 %0, t; }" : "=r"(a) : "l"(p));
    return a;
}
#define CP_ASYNC16(dst, src) \
    asm volatile("cp.async.cg.shared.global [%0], [%1], 16;" :: "r"(dst), "l"(src) : "memory")
#define CP_COMMIT() asm volatile("cp.async.commit_group;" ::: "memory")
#define CP_WAIT1()  asm volatile("cp.async.wait_group 1;" ::: "memory")

__device__ __forceinline__ void mma8(float (&d)[4], const unsigned (&a)[4],
                                     unsigned b0, unsigned b1) {
    asm volatile(
        "mma.sync.aligned.m16n8k8.row.col.f32.tf32.tf32.f32 "
        "{%0,%1,%2,%3}, {%4,%5,%6,%7}, {%8,%9}, {%0,%1,%2,%3};\n"
        : "+f"(d[0]), "+f"(d[1]), "+f"(d[2]), "+f"(d[3])
        : "r"(a[0]), "r"(a[1]), "r"(a[2]), "r"(a[3]), "r"(b0), "r"(b1));
}

__device__ __forceinline__ float act_gelu(float h) {
    return 0.5f * h * (1.0f + erff(h * 0.70710678118654752f));
}
__device__ __forceinline__ float act_silu(float h) {
    return h / (1.0f + __expf(-h));
}

// ---------------- stage 0: prep (init + tf32 round-copy both weights) ---------
__global__ void prep_kernel(const float* __restrict__ W1,
                            const float* __restrict__ W2) {
    size_t i = (size_t)blockIdx.x * blockDim.x + threadIdx.x;
    if (i < NE) { g_cnt[i] = 0; g_cnt2[i] = 0; }
    if (i < MAXROWS) g_rowtok[i] = -1;
    const size_t n4 = (size_t)NE * D_MODEL * D_FF / 4;   // float4 count per weight
    size_t stride = (size_t)gridDim.x * blockDim.x;
    const float4* w1 = (const float4*)W1;
    const float4* w2 = (const float4*)W2;
    float4* o1 = (float4*)g_w1r;
    float4* o2 = (float4*)g_w2r;
    for (size_t j = i; j < n4; j += stride) {
        float4 a = w1[j];
        a.x = __uint_as_float(f2tf(a.x)); a.y = __uint_as_float(f2tf(a.y));
        a.z = __uint_as_float(f2tf(a.z)); a.w = __uint_as_float(f2tf(a.w));
        o1[j] = a;
        float4 b = w2[j];
        b.x = __uint_as_float(f2tf(b.x)); b.y = __uint_as_float(f2tf(b.y));
        b.z = __uint_as_float(f2tf(b.z)); b.w = __uint_as_float(f2tf(b.w));
        o2[j] = b;
    }
}

// ---------------- stage 1: gate (fp32 exact) ---------------------------------
__global__ void gate_kernel(const float* __restrict__ x,
                            const float* __restrict__ Wg,
                            const float* __restrict__ bg) {
    int wid = threadIdx.x >> 5, lane = threadIdx.x & 31;
    int t = blockIdx.x * 8 + wid;
    const float* xr = x + (size_t)t * D_MODEL;
    float acc[8] = {0, 0, 0, 0, 0, 0, 0, 0};
    for (int d = lane; d < D_MODEL; d += 32) {
        float xv = xr[d];
        const float4* w = (const float4*)(Wg + d * 8);
        float4 w0 = w[0], w1 = w[1];
        acc[0] += xv * w0.x; acc[1] += xv * w0.y;
        acc[2] += xv * w0.z; acc[3] += xv * w0.w;
        acc[4] += xv * w1.x; acc[5] += xv * w1.y;
        acc[6] += xv * w1.z; acc[7] += xv * w1.w;
    }
#pragma unroll
    for (int o = 16; o > 0; o >>= 1)
#pragma unroll
        for (int e = 0; e < 8; e++)
            acc[e] += __shfl_xor_sync(0xffffffffu, acc[e], o);
    if (lane == 0) {
        float v0 = -1e30f, v1 = -1e30f;
        int i0 = 0, i1 = 0;
#pragma unroll
        for (int e = 0; e < 8; e++) {
            float v = acc[e] + bg[e];
            if (v > v0) { v1 = v0; i1 = i0; v0 = v; i0 = e; }
            else if (v > v1) { v1 = v; i1 = e; }
        }
        float e1 = expf(v1 - v0);
        float inv = 1.0f / (1.0f + e1);
        g_tokE[t * 2]     = i0; g_tokW[t * 2]     = inv;
        g_tokE[t * 2 + 1] = i1; g_tokW[t * 2 + 1] = e1 * inv;
        atomicAdd(&g_cnt[i0], 1);
        atomicAdd(&g_cnt[i1], 1);
    }
}

// ---------------- stage 2: plan ------------------------------------------------
__global__ void plan_kernel() {
    if (threadIdx.x == 0 && blockIdx.x == 0) {
        int ofs = 0;
        for (int e = 0; e < NE; e++) {
            g_off[e] = ofs;
            int nt = (g_cnt[e] + 127) >> 7;
            int t0 = ofs >> 7;
            for (int j = 0; j < nt; j++) g_tileE[t0 + j] = e;
            ofs += nt << 7;
        }
        for (int t = ofs >> 7; t < MAXTILES; t++) g_tileE[t] = -1;
    }
}

// ---------------- stage 3: scatter ---------------------------------------------
__global__ void scatter_kernel() {
    int i = blockIdx.x * blockDim.x + threadIdx.x;
    if (i >= T_TOK * 2) return;
    int e = g_tokE[i];
    int s = atomicAdd(&g_cnt2[e], 1);
    int row = g_off[e] + s;
    g_rowtok[row] = i >> 1;
    g_loc[i] = row;
}

// ---------------- stage 3b: gather tokens (tf32-rounded, zero-padded) ----------
__global__ void gather_kernel(const float* __restrict__ x) {
    int row = blockIdx.x;
    int tok = g_rowtok[row];
    float4* dst = (float4*)(g_xg + (size_t)row * D_MODEL) + threadIdx.x;
    if (tok >= 0) {
        float4 v = ((const float4*)(x + (size_t)tok * D_MODEL))[threadIdx.x];
        v.x = __uint_as_float(f2tf(v.x));
        v.y = __uint_as_float(f2tf(v.y));
        v.z = __uint_as_float(f2tf(v.z));
        v.w = __uint_as_float(f2tf(v.w));
        *dst = v;
    } else {
        *dst = make_float4(0.f, 0.f, 0.f, 0.f);
    }
}

// ---------------- stage 4/5: tiled TF32 GEMM, cp.async 3-stage pipeline --------
// CTA 128(M) x 256(N) x 32(K-chunk), 256 threads, warp grid 2x4, warp tile 64x64.
// All inputs pre-rounded to tf32 -> main loop is pure cp.async, no conversions.
// Weight base pointer resolved from the DEVICE symbol inside the kernel (the
// R5 bug was passing the __device__ symbol's host-side address as an argument).
template <int KTOT, int LDB, bool FFN1_>
__global__ __launch_bounds__(256, 1) void ffn_mma(const float* __restrict__ bias) {
    constexpr int NT = LDB / 256;
    constexpr int NC = KTOT / 32;

    int bid = blockIdx.x;
    int gid = bid / (8 * NT), rem = bid % (8 * NT);
    int mt = gid * 8 + (rem & 7);
    int nt = rem >> 3;
    int e = g_tileE[mt];
    if (e < 0) return;

    extern __shared__ unsigned sm[];
    uint32_t sb = smem_u32(sm);

    int tid = threadIdx.x, lane = tid & 31, wid = tid >> 5;
    int wm = wid >> 2, wn = wid & 3;     // 2 x 4 warp grid
    int lr = lane >> 2, lc = lane & 3;
    int m0 = mt * 128, n0 = nt * 256;

    const float* Ab = FFN1_ ? g_xg : g_act;
    const float* Bw = FFN1_ ? g_w1r : g_w2r;       // device-side symbol (fix)
    const float* Bb = Bw + (size_t)e * KTOT * LDB + n0;
    float* Out = FFN1_ ? g_act : g_y;

    // producer addressing: A 128x32 f32 = 1024 f4 -> 4/thread; B 32x256 = 2048 f4 -> 8/thread
    int rA = tid >> 3, qA = tid & 7;
    int rB = tid >> 6, qB = tid & 63;
    const float* srcA[4];
    uint32_t dA[4];
#pragma unroll
    for (int t = 0; t < 4; t++) {
        int r = rA + 32 * t;
        srcA[t] = Ab + (size_t)(m0 + r) * KTOT + qA * 4;
        dA[t] = (uint32_t)(r * 36 + qA * 4) * 4;
    }
    const float* srcB[8];
    uint32_t dB[8];
#pragma unroll
    for (int t = 0; t < 8; t++) {
        int r = rB + 4 * t;
        srcB[t] = Bb + (size_t)r * LDB + qB * 4;
        dB[t] = (uint32_t)(ASZ + r * 264 + qB * 4) * 4;
    }

    auto issue = [&](int c) {
        if (c >= NC) return;
        uint32_t s0 = sb + (uint32_t)(c % NSTAGE) * STAGE_BYTES;
        size_t k0 = (size_t)c * 32;
#pragma unroll
        for (int t = 0; t < 4; t++) CP_ASYNC16(s0 + dA[t], srcA[t] + k0);
        size_t kb = k0 * LDB;
#pragma unroll
        for (int t = 0; t < 8; t++) CP_ASYNC16(s0 + dB[t], srcB[t] + kb);
    };

    float acc[4][8][4];
#pragma unroll
    for (int i = 0; i < 4; i++)
#pragma unroll
        for (int j = 0; j < 8; j++)
#pragma unroll
            for (int k = 0; k < 4; k++) acc[i][j][k] = 0.0f;

    issue(0); CP_COMMIT();
    issue(1); CP_COMMIT();

    for (int c = 0; c < NC; c++) {
        CP_WAIT1();
        __syncthreads();
        issue(c + 2);
        CP_COMMIT();

        const unsigned* a_ = sm + (c % NSTAGE) * STAGEW;
        const unsigned* b_ = a_ + ASZ;
#pragma unroll
        for (int ks = 0; ks < 4; ks++) {
            int kk = ks * 8;
            unsigned af[4][4];
#pragma unroll
            for (int mf = 0; mf < 4; mf++) {
                int mrow = wm * 64 + mf * 16 + lr;
                af[mf][0] = a_[(mrow)     * 36 + kk + lc];
                af[mf][1] = a_[(mrow + 8) * 36 + kk + lc];
                af[mf][2] = a_[(mrow)     * 36 + kk + lc + 4];
                af[mf][3] = a_[(mrow + 8) * 36 + kk + lc + 4];
            }
#pragma unroll
            for (int nf = 0; nf < 8; nf++) {
                int ncol = wn * 64 + nf * 8 + lr;
                unsigned b0 = b_[(kk + lc)     * 264 + ncol];
                unsigned b1 = b_[(kk + lc + 4) * 264 + ncol];
#pragma unroll
                for (int mf = 0; mf < 4; mf++)
                    mma8(acc[mf][nf], af[mf], b0, b1);
            }
        }
    }

    // epilogue: bias + (activation + tf32 re-round for FFN1), register -> global
    bool isGelu = !(e & 1);
    const float* bb = bias + (size_t)e * LDB + n0;
#pragma unroll
    for (int mf = 0; mf < 4; mf++) {
#pragma unroll
        for (int nf = 0; nf < 8; nf++) {
            int row = m0 + wm * 64 + mf * 16 + lr;
            int colL = wn * 64 + nf * 8 + 2 * lc;
            float b0v = bb[colL], b1v = bb[colL + 1];
            float v00 = acc[mf][nf][0] + b0v;
            float v01 = acc[mf][nf][1] + b1v;
            float v10 = acc[mf][nf][2] + b0v;
            float v11 = acc[mf][nf][3] + b1v;
            if (FFN1_) {
                if (isGelu) {
                    v00 = act_gelu(v00); v01 = act_gelu(v01);
                    v10 = act_gelu(v10); v11 = act_gelu(v11);
                } else {
                    v00 = act_silu(v00); v01 = act_silu(v01);
                    v10 = act_silu(v10); v11 = act_silu(v11);
                }
                v00 = __uint_as_float(f2tf(v00));
                v01 = __uint_as_float(f2tf(v01));
                v10 = __uint_as_float(f2tf(v10));
                v11 = __uint_as_float(f2tf(v11));
            }
            float* op = Out + (size_t)row * LDB + n0 + colL;
            *(float2*)op = make_float2(v00, v01);
            *(float2*)(op + (size_t)8 * LDB) = make_float2(v10, v11);
        }
    }
}

// ---------------- stage 6: combine ---------------------------------------------
__global__ void combine_kernel(float* __restrict__ out) {
    int t = blockIdx.x, c = threadIdx.x;
    float w0 = g_tokW[t * 2], w1 = g_tokW[t * 2 + 1];
    int l0 = g_loc[t * 2], l1 = g_loc[t * 2 + 1];
    const float4 y0 = *(const float4*)(g_y + (size_t)l0 * D_MODEL + c * 4);
    const float4 y1 = *(const float4*)(g_y + (size_t)l1 * D_MODEL + c * 4);
    float4 o;
    o.x = w0 * y0.x + w1 * y1.x;
    o.y = w0 * y0.y + w1 * y1.y;
    o.z = w0 * y0.z + w1 * y1.z;
    o.w = w0 * y0.w + w1 * y1.w;
    *(float4*)(out + (size_t)t * D_MODEL + c * 4) = o;
}

// ---------------- host launcher -------------------------------------------------
extern "C" void kernel_launch(void* const* d_in, const int* in_sizes, int n_in,
                              void* d_out, int out_size) {
    const float* x  = (const float*)d_in[0];
    const float* W1 = (const float*)d_in[1];
    const float* b1 = (const float*)d_in[2];
    const float* W2 = (const float*)d_in[3];
    const float* b2 = (const float*)d_in[4];
    const float* Wg = (const float*)d_in[5];
    const float* bg = (const float*)d_in[6];
    float* out = (float*)d_out;

    cudaFuncSetAttribute(ffn_mma<D_MODEL, D_FF, true>,
                         cudaFuncAttributeMaxDynamicSharedMemorySize, SMEM_TOTAL);
    cudaFuncSetAttribute(ffn_mma<D_FF, D_MODEL, false>,
                         cudaFuncAttributeMaxDynamicSharedMemorySize, SMEM_TOTAL);

    // launch order keeps ffn1 at index 5 (0-based) so ncu -s 5 -c 1 captures it
    prep_kernel<<<2048, 256>>>(W1, W2);                      // 0
    gate_kernel<<<T_TOK / 8, 256>>>(x, Wg, bg);              // 1
    plan_kernel<<<1, 1>>>();                                 // 2
    scatter_kernel<<<(T_TOK * 2) / 256, 256>>>();            // 3
    gather_kernel<<<MAXROWS, 256>>>(x);                      // 4
    // FFN1: 72 m-tiles x 16 n-tiles (N=256)
    ffn_mma<D_MODEL, D_FF, true>                             // 5
        <<<MAXTILES * (D_FF / 256), 256, SMEM_TOTAL>>>(b1);
    // FFN2: 72 m-tiles x 4 n-tiles
    ffn_mma<D_FF, D_MODEL, false>                            // 6
        <<<MAXTILES * (D_MODEL / 256), 256, SMEM_TOTAL>>>(b2);
    combine_kernel<<<T_TOK, 256>>>(out);                     // 7
}